// round 9
// baseline (speedup 1.0000x reference)
#include <cuda_runtime.h>

#define TT   512
#define BB   2048
#define NTAG 16
#define LOG2E 1.4426950408889634f

// scratch: h sequence (T, B, 4) fp32 = 16.8 MB
__device__ float g_h[(size_t)TT * BB * 4];
// scratch: precomputed x-part of gate preactivations, [t][b][g][k] = 67 MB
__device__ float g_prex[(size_t)TT * BB * 16];

__device__ __forceinline__ float rcp_ap(float x)  { float r; asm("rcp.approx.f32 %0, %1;"  : "=f"(r) : "f"(x)); return r; }
__device__ __forceinline__ float ex2_ap(float x)  { float r; asm("ex2.approx.f32 %0, %1;"  : "=f"(r) : "f"(x)); return r; }
__device__ __forceinline__ float lg2_ap(float x)  { float r; asm("lg2.approx.f32 %0, %1;"  : "=f"(r) : "f"(x)); return r; }
__device__ __forceinline__ float cos_ap(float x)  { float r; asm("cos.approx.f32 %0, %1;"  : "=f"(r) : "f"(x)); return r; }

// ---------------------------------------------------------------------------
// Kernel P: pre-pass. pre_x[t,b,g,k] = sum_d x[t,b,d]*wx[g,k,d] + th[g,k].
// One thread per (row, g): 4M threads, 32 FMA each. Memory-bound (~100MB).
// Same fmaf ordering as the recurrence previously used -> identical numerics.
// ---------------------------------------------------------------------------
__global__ void __launch_bounds__(256)
pre_kernel(const float* __restrict__ x,
           const float* __restrict__ w_gates,
           const float* __restrict__ b_gates,
           const float* __restrict__ rx_theta)
{
    int gt  = blockIdx.x * 256 + threadIdx.x;    // 0 .. 4*TT*BB-1
    int row = gt >> 2;                           // (t*BB + b)
    int g   = gt & 3;

    float wx[4][8], th[4];
#pragma unroll
    for (int k = 0; k < 4; k++) {
#pragma unroll
        for (int d = 0; d < 8; d++) wx[k][d] = w_gates[g*48 + k*12 + d];
        th[k] = b_gates[g*4 + k] + rx_theta[g*4 + k];
    }

    const float4* xv4 = (const float4*)x + (size_t)row * 2;
    float4 A = xv4[0], B = xv4[1];
    float xv[8] = {A.x, A.y, A.z, A.w, B.x, B.y, B.z, B.w};

    float o[4];
#pragma unroll
    for (int k = 0; k < 4; k++) {
        float q = fmaf(xv[0], wx[k][0], th[k]);
        q = fmaf(xv[1], wx[k][1], q); q = fmaf(xv[2], wx[k][2], q);
        q = fmaf(xv[3], wx[k][3], q); q = fmaf(xv[4], wx[k][4], q);
        q = fmaf(xv[5], wx[k][5], q); q = fmaf(xv[6], wx[k][6], q);
        o[k] = fmaf(xv[7], wx[k][7], q);
    }
    ((float4*)g_prex)[(size_t)row * 4 + g] = make_float4(o[0], o[1], o[2], o[3]);
}

// ---------------------------------------------------------------------------
// Kernel A: the LSTM recurrence. Exactly the R4 structure (best known), with
// the per-step 70-instruction x·W block replaced by one LDG.128 from g_prex
// through a 4-deep register ring (prefetch distance 4 steps >> mem latency).
// ---------------------------------------------------------------------------
__global__ void __launch_bounds__(32, 1)
recur_kernel(const float* __restrict__ w_gates)
{
    const int tid = blockIdx.x * 32 + threadIdx.x;   // 0..8191
    const int b   = tid >> 2;                        // batch chain 0..2047
    const int g   = tid & 3;                         // gate (f,i,g,o)

    // recurrent weights only: wh[k][j] = w_gates[g*48 + k*12 + 8 + j]
    float wh[4][4];
#pragma unroll
    for (int k = 0; k < 4; k++)
#pragma unroll
        for (int j = 0; j < 4; j++) wh[k][j] = w_gates[g*48 + k*12 + 8 + j];

    // lane 2 is the tanh gate; lanes 0,1,3 are sigmoid gates
    const float gm = (g == 2) ?  2.0f * LOG2E : -LOG2E;
    const float gA = (g == 2) ? -2.0f         :  1.0f;
    const float gB = (g == 2) ?  1.0f         :  0.0f;

    float h0 = 0.f, h1 = 0.f, h2 = 0.f, h3 = 0.f;
    float cx[4] = {0.f, 0.f, 0.f, 0.f};

    // 4-deep prefetch ring over pre_x; lane reads float4 at (t*BB+b)*4+g
    const float4* pxp = (const float4*)g_prex;
    const size_t lofs = (size_t)b * 4 + g;
    float4 pa[4];
#pragma unroll
    for (int p = 0; p < 4; p++)
        pa[p] = pxp[(size_t)p * (BB*4) + lofs];

    float4* hout = (float4*)g_h;

#pragma unroll 4
    for (int t = 0; t < TT; t++) {
        const int slot = t & 3;
        float4 xc = pa[slot];

        // ---- pre = xacc + Wh·h ; c = cos(pre) (h-critical path) ----
        float c0, c1, c2, c3;
        {
            float s0, s1;
            s0 = fmaf(h1, wh[0][1], fmaf(h0, wh[0][0], xc.x));
            s1 = fmaf(h3, wh[0][3], h2 * wh[0][2]);
            c0 = cos_ap(s0 + s1);
            s0 = fmaf(h1, wh[1][1], fmaf(h0, wh[1][0], xc.y));
            s1 = fmaf(h3, wh[1][3], h2 * wh[1][2]);
            c1 = cos_ap(s0 + s1);
            s0 = fmaf(h1, wh[2][1], fmaf(h0, wh[2][0], xc.z));
            s1 = fmaf(h3, wh[2][3], h2 * wh[2][2]);
            c2 = cos_ap(s0 + s1);
            s0 = fmaf(h1, wh[3][1], fmaf(h0, wh[3][0], xc.w));
            s1 = fmaf(h3, wh[3][3], h2 * wh[3][2]);
            c3 = cos_ap(s0 + s1);
        }

        // ---- off-path: refill ring slot with pre_x[t+4] ----
        {
            int tp = t + 4; if (tp > TT - 1) tp = TT - 1;
            pa[slot] = pxp[(size_t)tp * (BB*4) + lofs];
        }

        // ---- expvals: e0=c1c2c3, e1=c0c1, e2=e1c2, e3=e1t23 ----
        float t23 = c2 * c3;
        float e1  = c0 * c1;
        float e0  = c1 * t23;
        float e2  = e1 * c2;
        float e3  = e1 * t23;

        // ---- gate nonlinearity (exact): v = fma(A, rcp(ex2(m*e)+1), B) ----
        float v0 = fmaf(gA, rcp_ap(ex2_ap(gm * e0) + 1.0f), gB);
        float v1 = fmaf(gA, rcp_ap(ex2_ap(gm * e1) + 1.0f), gB);
        float v2 = fmaf(gA, rcp_ap(ex2_ap(gm * e2) + 1.0f), gB);
        float v3 = fmaf(gA, rcp_ap(ex2_ap(gm * e3) + 1.0f), gB);

        // ---- gather all 4 gate vectors into every lane (16 independent shfl) ----
        float tg0[4], tg1[4], tg2[4], tg3[4];
#pragma unroll
        for (int s = 0; s < 4; s++) {
            tg0[s] = __shfl_sync(0xffffffffu, v0, s, 4);
            tg1[s] = __shfl_sync(0xffffffffu, v1, s, 4);
            tg2[s] = __shfl_sync(0xffffffffu, v2, s, 4);
            tg3[s] = __shfl_sync(0xffffffffu, v3, s, 4);
        }
        // tgK[s] = gate-s value for wire K. s: 0=f, 1=i, 2=g, 3=o.

        // ---- combine (replicated in all lanes) ----
        float hn[4];
#pragma unroll
        for (int k = 0; k < 4; k++) {
            float F = (k==0)?tg0[0]:(k==1)?tg1[0]:(k==2)?tg2[0]:tg3[0];
            float I = (k==0)?tg0[1]:(k==1)?tg1[1]:(k==2)?tg2[1]:tg3[1];
            float G = (k==0)?tg0[2]:(k==1)?tg1[2]:(k==2)?tg2[2]:tg3[2];
            float O = (k==0)?tg0[3]:(k==1)?tg1[3]:(k==2)?tg2[3]:tg3[3];
            float nc = fmaf(F, cx[k], I * G);
            cx[k] = nc;
            // tanh(cx) = 1 - 2/(exp(2cx)+1)
            float E  = ex2_ap(nc * (2.0f * LOG2E));
            float r  = rcp_ap(E + 1.0f);
            float tc = fmaf(-2.0f, r, 1.0f);
            hn[k] = O * tc;                              // o * tanh(cx)
        }
        h0 = hn[0]; h1 = hn[1]; h2 = hn[2]; h3 = hn[3];

        if (g == 0)
            hout[(size_t)t * BB + b] = make_float4(h0, h1, h2, h3);
    }
}

// ---------------------------------------------------------------------------
// Kernel B: logits + log_softmax. 2 threads per row-half (8 tags each),
// 4 rows per thread; softmax max/sum joined via shfl_xor within lane pair.
// ---------------------------------------------------------------------------
__global__ void __launch_bounds__(256)
out_kernel(const float* __restrict__ w_tag,
           const float* __restrict__ b_tag,
           float* __restrict__ out)
{
    const int NPAIR = TT * BB / 4;               // 262144 rows per chunk
    int gt   = blockIdx.x * 256 + threadIdx.x;   // 0 .. 524287
    int p    = gt >> 1;                          // base row
    int half = gt & 1;

    const float4* wt = (const float4*)w_tag;     // 16 rows of float4
    float4 w[8];
#pragma unroll
    for (int j = 0; j < 8; j++) w[j] = wt[half*8 + j];
    float4 bta = ((const float4*)b_tag)[half*2];
    float4 btb = ((const float4*)b_tag)[half*2 + 1];
    float bt[8] = {bta.x, bta.y, bta.z, bta.w, btb.x, btb.y, btb.z, btb.w};

    const float4* hv4 = (const float4*)g_h;
    float4* o4 = (float4*)out;

#pragma unroll
    for (int it = 0; it < 4; it++) {
        int row = p + it * NPAIR;
        float4 hv = hv4[row];
        float lg[8];
#pragma unroll
        for (int j = 0; j < 8; j++)
            lg[j] = fmaf(w[j].w, hv.w, fmaf(w[j].z, hv.z, fmaf(w[j].y, hv.y, fmaf(w[j].x, hv.x, bt[j]))));

        float m = lg[0];
#pragma unroll
        for (int j = 1; j < 8; j++) m = fmaxf(m, lg[j]);
        m = fmaxf(m, __shfl_xor_sync(0xffffffffu, m, 1));

        float s = 0.f;
#pragma unroll
        for (int j = 0; j < 8; j++) s += ex2_ap((lg[j] - m) * LOG2E);
        s += __shfl_xor_sync(0xffffffffu, s, 1);

        float ls = fmaf(lg2_ap(s), 0.6931471805599453f, m);

        o4[(size_t)row*4 + half*2 + 0] = make_float4(lg[0]-ls, lg[1]-ls, lg[2]-ls, lg[3]-ls);
        o4[(size_t)row*4 + half*2 + 1] = make_float4(lg[4]-ls, lg[5]-ls, lg[6]-ls, lg[7]-ls);
    }
}

extern "C" void kernel_launch(void* const* d_in, const int* in_sizes, int n_in,
                              void* d_out, int out_size)
{
    const float* x        = (const float*)d_in[0];
    const float* w_gates  = (const float*)d_in[1];
    const float* b_gates  = (const float*)d_in[2];
    const float* rx_theta = (const float*)d_in[3];
    const float* w_tag    = (const float*)d_in[4];
    const float* b_tag    = (const float*)d_in[5];

    pre_kernel<<<16384, 256>>>(x, w_gates, b_gates, rx_theta);  // 4 threads / (t,b)
    recur_kernel<<<256, 32>>>(w_gates);                          // 8192 threads (R4 layout)
    out_kernel<<<2048, 256>>>(w_tag, b_tag, (float*)d_out);      // 4 rows per thread-pair
}

// round 10
// speedup vs baseline: 1.1132x; 1.1132x over previous
#include <cuda_runtime.h>

#define TT   512
#define BB   2048
#define NTAG 16
#define LOG2E 1.4426950408889634f

// scratch: h sequence (T, B, 4) fp32 = 16.8 MB
__device__ float g_h[(size_t)TT * BB * 4];
// scratch: precomputed x-part of gate preactivations, [t][b][g][k] = 67 MB
__device__ float g_prex[(size_t)TT * BB * 16];

__device__ __forceinline__ float rcp_ap(float x)  { float r; asm("rcp.approx.f32 %0, %1;"  : "=f"(r) : "f"(x)); return r; }
__device__ __forceinline__ float ex2_ap(float x)  { float r; asm("ex2.approx.f32 %0, %1;"  : "=f"(r) : "f"(x)); return r; }
__device__ __forceinline__ float lg2_ap(float x)  { float r; asm("lg2.approx.f32 %0, %1;"  : "=f"(r) : "f"(x)); return r; }
__device__ __forceinline__ float cos_ap(float x)  { float r; asm("cos.approx.f32 %0, %1;"  : "=f"(r) : "f"(x)); return r; }

// Pade[5/4] tanh: tanh(u) = u*(q^2+105q+945)/(15q^2+420q+945), q=u^2.
// |err| <= ~5e-8 on |u|<=1 (inputs here are products of cosines, |u|<=1).
__device__ __forceinline__ float tanh_pade(float u) {
    float q = u * u;
    float n = fmaf(q + 105.0f, q, 945.0f) * u;
    float d = fmaf(fmaf(q, 15.0f, 420.0f), q, 945.0f);
    return n * rcp_ap(d);
}

// ---------------------------------------------------------------------------
// Kernel P: pre-pass. pre_x[t,b,g,k] = sum_d x[t,b,d]*wx[g,k,d] + th[g,k].
// Thread = (g, 4 rows): weight loads amortized 4x, float4 weight loads
// (w_gates rows are 16B-aligned: g*48+k*12 is divisible by 4 floats).
// ---------------------------------------------------------------------------
__global__ void __launch_bounds__(256)
pre_kernel(const float* __restrict__ x,
           const float* __restrict__ w_gates,
           const float* __restrict__ b_gates,
           const float* __restrict__ rx_theta)
{
    const int NQ = TT * BB / 4;                  // rows per chunk
    int gt  = blockIdx.x * 256 + threadIdx.x;    // 0 .. TT*BB-1
    int p   = gt >> 2;                           // base row
    int g   = gt & 3;

    float wx[4][8], th[4];
#pragma unroll
    for (int k = 0; k < 4; k++) {
        const float4* wr = (const float4*)(w_gates + g*48 + k*12);
        float4 w0 = wr[0], w1 = wr[1];
        wx[k][0]=w0.x; wx[k][1]=w0.y; wx[k][2]=w0.z; wx[k][3]=w0.w;
        wx[k][4]=w1.x; wx[k][5]=w1.y; wx[k][6]=w1.z; wx[k][7]=w1.w;
        th[k] = b_gates[g*4 + k] + rx_theta[g*4 + k];
    }

#pragma unroll
    for (int it = 0; it < 4; it++) {
        int row = p + it * NQ;
        const float4* xv4 = (const float4*)x + (size_t)row * 2;
        float4 A = xv4[0], B = xv4[1];
        float xv[8] = {A.x, A.y, A.z, A.w, B.x, B.y, B.z, B.w};

        float o[4];
#pragma unroll
        for (int k = 0; k < 4; k++) {
            float q = fmaf(xv[0], wx[k][0], th[k]);
            q = fmaf(xv[1], wx[k][1], q); q = fmaf(xv[2], wx[k][2], q);
            q = fmaf(xv[3], wx[k][3], q); q = fmaf(xv[4], wx[k][4], q);
            q = fmaf(xv[5], wx[k][5], q); q = fmaf(xv[6], wx[k][6], q);
            o[k] = fmaf(xv[7], wx[k][7], q);
        }
        ((float4*)g_prex)[(size_t)row * 4 + g] = make_float4(o[0], o[1], o[2], o[3]);
    }
}

// ---------------------------------------------------------------------------
// Kernel A: LSTM recurrence. 4 lanes per chain (one per gate g).
// MUFU/step = 10 (4 cos + 4 Pade-rcp + 2 combine), SHFL/step = 7
// (4-shfl butterfly transpose + 3-shfl h allgather). x-part preloaded
// from g_prex via a 4-deep LDG.128 ring. Layout: 256 blocks x 32 thr (R4).
// ---------------------------------------------------------------------------
__global__ void __launch_bounds__(32, 1)
recur_kernel(const float* __restrict__ w_gates)
{
    const int tid = blockIdx.x * 32 + threadIdx.x;   // 0..8191
    const int b   = tid >> 2;                        // batch chain 0..2047
    const int g   = tid & 3;                         // gate (f,i,g,o)
    const bool hi1 = (g & 1), hi2 = (g & 2);

    // recurrent weights only: wh[k][j] = w_gates[g*48 + k*12 + 8 + j]
    float wh[4][4];
#pragma unroll
    for (int k = 0; k < 4; k++)
#pragma unroll
        for (int j = 0; j < 4; j++) wh[k][j] = w_gates[g*48 + k*12 + 8 + j];

    // lane 2 = tanh gate; lanes 0,1,3 = sigmoid: sig(e) = 0.5 + 0.5*tanh(e/2)
    const float gm = (g == 2) ? 1.0f : 0.5f;   // folded into c1
    const float gA = (g == 2) ? 1.0f : 0.5f;
    const float gB = (g == 2) ? 0.0f : 0.5f;

    float h0 = 0.f, h1 = 0.f, h2 = 0.f, h3 = 0.f;
    float cx = 0.f;                                  // own wire's cell state

    // 4-deep prefetch ring over pre_x; lane reads float4 at (t*BB+b)*4+g
    const float4* pxp = (const float4*)g_prex;
    const size_t lofs = (size_t)b * 4 + g;
    float4 pa[4];
#pragma unroll
    for (int p = 0; p < 4; p++)
        pa[p] = pxp[(size_t)p * (BB*4) + lofs];

    float* hout = g_h + lofs;                        // own-wire store

#pragma unroll 4
    for (int t = 0; t < TT; t++) {
        const int slot = t & 3;
        float4 xc = pa[slot];

        // ---- pre = xc + Wh·h ; c = cos(pre) (h-critical path) ----
        float c0, c1, c2, c3;
        {
            float s0, s1;
            s0 = fmaf(h1, wh[0][1], fmaf(h0, wh[0][0], xc.x));
            s1 = fmaf(h3, wh[0][3], h2 * wh[0][2]);
            c0 = cos_ap(s0 + s1);
            s0 = fmaf(h1, wh[1][1], fmaf(h0, wh[1][0], xc.y));
            s1 = fmaf(h3, wh[1][3], h2 * wh[1][2]);
            c1 = cos_ap(s0 + s1);
            s0 = fmaf(h1, wh[2][1], fmaf(h0, wh[2][0], xc.z));
            s1 = fmaf(h3, wh[2][3], h2 * wh[2][2]);
            c2 = cos_ap(s0 + s1);
            s0 = fmaf(h1, wh[3][1], fmaf(h0, wh[3][0], xc.w));
            s1 = fmaf(h3, wh[3][3], h2 * wh[3][2]);
            c3 = cos_ap(s0 + s1);
        }

        // ---- off-path: refill ring slot with pre_x[t+4] ----
        {
            int tp = t + 4; if (tp > TT - 1) tp = TT - 1;
            pa[slot] = pxp[(size_t)tp * (BB*4) + lofs];
        }

        // ---- expvals with gm folded into c1: u_k = gate input (pre-tanh) ----
        float c1s = gm * c1;
        float t23 = c2 * c3;
        float u1  = c0 * c1s;
        float u0  = c1s * t23;
        float u2  = u1 * c2;
        float u3  = u1 * t23;

        // ---- gate nonlinearity: v = fma(A, tanh_pade(u), B)  (1 MUFU each) ----
        float v0 = fmaf(gA, tanh_pade(u0), gB);
        float v1 = fmaf(gA, tanh_pade(u1), gB);
        float v2 = fmaf(gA, tanh_pade(u2), gB);
        float v3 = fmaf(gA, tanh_pade(u3), gB);

        // ---- butterfly 4x4 transpose: lane g ends with (F,I,G,O) of wire g ----
        float s0 = hi2 ? v0 : v2;
        float s1 = hi2 ? v1 : v3;
        float r0 = __shfl_xor_sync(0xffffffffu, s0, 2);
        float r1 = __shfl_xor_sync(0xffffffffu, s1, 2);
        float a0 = hi2 ? r0 : v0;
        float a1 = hi2 ? r1 : v1;
        float a2 = hi2 ? v2 : r0;
        float a3 = hi2 ? v3 : r1;
        float t0 = hi1 ? a0 : a1;
        float t1 = hi1 ? a2 : a3;
        float q0 = __shfl_xor_sync(0xffffffffu, t0, 1);
        float q1 = __shfl_xor_sync(0xffffffffu, t1, 1);
        float F = hi1 ? q0 : a0;
        float I = hi1 ? a1 : q0;
        float G = hi1 ? q1 : a2;
        float O = hi1 ? a3 : q1;

        // ---- single-wire combine (wire g) ----
        float nc = fmaf(F, cx, I * G);
        cx = nc;
        float E  = ex2_ap(nc * (2.0f * LOG2E));   // tanh(cx) = 1 - 2/(exp(2cx)+1)
        float rr = rcp_ap(E + 1.0f);
        float tc = fmaf(-2.0f, rr, 1.0f);
        float h  = O * tc;

        hout[(size_t)t * (BB * 4)] = h;           // warp: 128B contiguous

        // ---- butterfly allgather of h across the quad (3 shfl) ----
        float hp  = __shfl_xor_sync(0xffffffffu, h, 1);
        float hA0 = hi1 ? hp : h;
        float hA1 = hi1 ? h  : hp;
        float sA0 = __shfl_xor_sync(0xffffffffu, hA0, 2);
        float sA1 = __shfl_xor_sync(0xffffffffu, hA1, 2);
        h0 = hi2 ? sA0 : hA0;
        h1 = hi2 ? sA1 : hA1;
        h2 = hi2 ? hA0 : sA0;
        h3 = hi2 ? hA1 : sA1;
    }
}

// ---------------------------------------------------------------------------
// Kernel B: logits + log_softmax. 2 threads per row-half (8 tags each),
// 4 rows per thread; softmax max/sum joined via shfl_xor within lane pair.
// ---------------------------------------------------------------------------
__global__ void __launch_bounds__(256)
out_kernel(const float* __restrict__ w_tag,
           const float* __restrict__ b_tag,
           float* __restrict__ out)
{
    const int NPAIR = TT * BB / 4;               // 262144 rows per chunk
    int gt   = blockIdx.x * 256 + threadIdx.x;   // 0 .. 524287
    int p    = gt >> 1;                          // base row
    int half = gt & 1;

    const float4* wt = (const float4*)w_tag;     // 16 rows of float4
    float4 w[8];
#pragma unroll
    for (int j = 0; j < 8; j++) w[j] = wt[half*8 + j];
    float4 bta = ((const float4*)b_tag)[half*2];
    float4 btb = ((const float4*)b_tag)[half*2 + 1];
    float bt[8] = {bta.x, bta.y, bta.z, bta.w, btb.x, btb.y, btb.z, btb.w};

    const float4* hv4 = (const float4*)g_h;
    float4* o4 = (float4*)out;

#pragma unroll
    for (int it = 0; it < 4; it++) {
        int row = p + it * NPAIR;
        float4 hv = hv4[row];
        float lg[8];
#pragma unroll
        for (int j = 0; j < 8; j++)
            lg[j] = fmaf(w[j].w, hv.w, fmaf(w[j].z, hv.z, fmaf(w[j].y, hv.y, fmaf(w[j].x, hv.x, bt[j]))));

        float m = lg[0];
#pragma unroll
        for (int j = 1; j < 8; j++) m = fmaxf(m, lg[j]);
        m = fmaxf(m, __shfl_xor_sync(0xffffffffu, m, 1));

        float s = 0.f;
#pragma unroll
        for (int j = 0; j < 8; j++) s += ex2_ap((lg[j] - m) * LOG2E);
        s += __shfl_xor_sync(0xffffffffu, s, 1);

        float ls = fmaf(lg2_ap(s), 0.6931471805599453f, m);

        o4[(size_t)row*4 + half*2 + 0] = make_float4(lg[0]-ls, lg[1]-ls, lg[2]-ls, lg[3]-ls);
        o4[(size_t)row*4 + half*2 + 1] = make_float4(lg[4]-ls, lg[5]-ls, lg[6]-ls, lg[7]-ls);
    }
}

extern "C" void kernel_launch(void* const* d_in, const int* in_sizes, int n_in,
                              void* d_out, int out_size)
{
    const float* x        = (const float*)d_in[0];
    const float* w_gates  = (const float*)d_in[1];
    const float* b_gates  = (const float*)d_in[2];
    const float* rx_theta = (const float*)d_in[3];
    const float* w_tag    = (const float*)d_in[4];
    const float* b_tag    = (const float*)d_in[5];

    pre_kernel<<<4096, 256>>>(x, w_gates, b_gates, rx_theta);   // 4 rows / thread
    recur_kernel<<<256, 32>>>(w_gates);                          // 8192 threads
    out_kernel<<<2048, 256>>>(w_tag, b_tag, (float*)d_out);      // 4 rows / thread-pair
}